// round 1
// baseline (speedup 1.0000x reference)
#include <cuda_runtime.h>
#include <math.h>

#define NPASS 16
#define NVERT 642
#define NFACE 640
#define IMH 160
#define IMW 160
#define HW (IMH*IMW)

// ---------------- scratch (device globals; no allocation) ----------------
__device__ float  g_R[NPASS*9];
__device__ float  g_toff[NPASS*3];
__device__ float  g_gauss[11];
__device__ float  g_focal;
__device__ float  g_verts[NPASS*NVERT*3];
__device__ float4 g_faceb[NPASS*NFACE*4];
__device__ int    g_nvalid[NPASS];
__device__ float  g_feats[NPASS*3*HW];
__device__ float  g_soft[NPASS*HW];
__device__ float  g_mask[NPASS*HW];
__device__ float  g_tmpA[NPASS*3*HW];
__device__ float  g_tmpB[NPASS*HW];
__device__ float  g_tmpC[NPASS*HW];

// ---------------- setup: rotations, offsets, constants ----------------
__device__ void quat_rod(const float* q, float scale, float* R){
    float w=q[0], x=q[1], y=q[2], z=q[3];
    float sn=sqrtf(x*x+y*y+z*z);
    float tt = 2.0f*((w<0.0f)? atan2f(-sn,-w) : atan2f(sn,w));
    float k = (sn>1e-8f)? (tt/fmaxf(sn,1e-8f)) : 2.0f;
    k *= scale;
    float ax=x*k, ay=y*k, az=z*k;
    float th=sqrtf(ax*ax+ay*ay+az*az);
    float inv=1.0f/fmaxf(th,1e-8f);
    float ux=ax*inv, uy=ay*inv, uz=az*inv;
    float s=sinf(th), c=cosf(th), cc=1.0f-c;
    R[0]=1.0f+cc*(-(uy*uy+uz*uz)); R[1]=-s*uz+cc*(ux*uy);          R[2]= s*uy+cc*(ux*uz);
    R[3]= s*uz+cc*(ux*uy);         R[4]=1.0f+cc*(-(ux*ux+uz*uz));  R[5]=-s*ux+cc*(uy*uz);
    R[6]=-s*uy+cc*(ux*uz);         R[7]= s*ux+cc*(uy*uz);          R[8]=1.0f+cc*(-(ux*ux+uy*uy));
}

__global__ void k_setup(const float* __restrict__ quat, const float* __restrict__ trans){
    if(threadIdx.x!=0 || blockIdx.x!=0) return;
    // gaussian kernel (match numpy float64 then cast)
    double s=0.0; double gg[11];
    for(int i=0;i<11;i++){ double xx=(double)(i-5); gg[i]=exp(-0.5*xx*xx); s+=gg[i]; }
    for(int i=0;i<11;i++) g_gauss[i]=(float)(gg[i]/s);
    g_focal=(float)(1.0/tan(1.57/4.0));
    for(int f=0; f<2; f++){
        float R[9], Rs[9];
        quat_rod(&quat[(f*2+1)*4], 1.0f, R);
        quat_rod(&quat[(f*2+0)*4], 1.0f/16.0f, Rs);   // /(FMO_STEPS*2)
        for(int st=0; st<8; st++){
            int p=f*8+st;
            for(int i=0;i<9;i++) g_R[p*9+i]=R[i];
            float ti=(float)st*(1.0f/7.0f);
            for(int k=0;k<3;k++)
                g_toff[p*3+k]=trans[(f*2+1)*3+k] + ti*trans[(f*2+0)*3+k] - ((k==2)?2.0f:0.0f);
            float Rn[9];
            for(int i=0;i<3;i++)
                for(int j=0;j<3;j++)
                    Rn[i*3+j]=R[i*3+0]*Rs[0*3+j]+R[i*3+1]*Rs[1*3+j]+R[i*3+2]*Rs[2*3+j];
            for(int i=0;i<9;i++) R[i]=Rn[i];
        }
    }
}

// ---------------- vertex transform (camera space) ----------------
__global__ void k_verts(const float* __restrict__ uv){
    int p=blockIdx.x; int n=threadIdx.x;
    if(n>=NVERT) return;
    const float* R=&g_R[p*9];
    const float* t=&g_toff[p*3];
    float ux=uv[n*3+0], uy=uv[n*3+1], uz=uv[n*3+2];
    float* o=&g_verts[(p*NVERT+n)*3];
    o[0]=R[0]*ux+R[1]*uy+R[2]*uz + t[0];
    o[1]=R[3]*ux+R[4]*uy+R[5]*uz + t[1];
    o[2]=R[6]*ux+R[7]*uy+R[8]*uz + t[2];
}

// ---------------- per-face setup + stable compaction ----------------
__global__ void k_faces(const int* __restrict__ faces){
    int p=blockIdx.x; int i=threadIdx.x;   // blockDim == 640
    int lane=i&31, wid=i>>5;
    __shared__ int wcnt[20];
    __shared__ int wbase[20];
    int i0=faces[i*3+0], i1=faces[i*3+1], i2=faces[i*3+2];
    const float* vb=&g_verts[p*NVERT*3];
    float ax3=vb[i0*3], ay3=vb[i0*3+1], az3=vb[i0*3+2];
    float bx3=vb[i1*3], by3=vb[i1*3+1], bz3=vb[i1*3+2];
    float cx3=vb[i2*3], cy3=vb[i2*3+1], cz3=vb[i2*3+2];
    float nz=(bx3-ax3)*(cy3-ay3)-(by3-ay3)*(cx3-ax3);
    float F=g_focal;
    float ax=(ax3*F)/(-az3), ay=(ay3*F)/(-az3);
    float bx=(bx3*F)/(-bz3), by=(by3*F)/(-bz3);
    float cx=(cx3*F)/(-cz3), cy=(cy3*F)/(-cz3);
    float denom=(bx-ax)*(cy-ay)-(by-ay)*(cx-ax);
    bool valid=(nz>0.0f)&&(fabsf(denom)>1e-9f);
    unsigned bal=__ballot_sync(0xffffffffu, valid);
    if(lane==0) wcnt[wid]=__popc(bal);
    __syncthreads();
    if(i==0){
        int acc=0;
        for(int w=0;w<20;w++){ wbase[w]=acc; acc+=wcnt[w]; }
        g_nvalid[p]=acc;
    }
    __syncthreads();
    if(valid){
        int pos=wbase[wid]+__popc(bal&((1u<<lane)-1u));
        float inv=1.0f/denom;  // |denom|>1e-9 here, so dsafe==denom
        float4* rec=&g_faceb[(p*NFACE+pos)*4];
        rec[0]=make_float4((bx*cy-by*cx)*inv, (by-cy)*inv, (cx-bx)*inv, az3);
        rec[1]=make_float4((cx*ay-cy*ax)*inv, (cy-ay)*inv, (ax-cx)*inv, bz3);
        rec[2]=make_float4((ax*by-ay*bx)*inv, (ay-by)*inv, (bx-ax)*inv, cz3);
        rec[3]=make_float4(__int_as_float(i), 0.f, 0.f, 0.f);
    }
}

// ---------------- rasterizer ----------------
__global__ void __launch_bounds__(256) k_raster(const float* __restrict__ ffeat){
    int p=blockIdx.z;
    int x=blockIdx.x*16+threadIdx.x;
    int y=blockIdx.y*16+threadIdx.y;
    __shared__ float4 sf[NFACE*4];   // 40 KB
    int n=g_nvalid[p];
    const float4* src=&g_faceb[p*NFACE*4];
    int tid=threadIdx.y*16+threadIdx.x;
    for(int i=tid;i<n*4;i+=256) sf[i]=src[i];
    __syncthreads();
    float px=fmaf((float)x,  2.0f/159.0f, -1.0f);
    float py=fmaf((float)y, -2.0f/159.0f,  1.0f);
    float bz=-1e9f, bw0=0.f, bw1=0.f, bw2=0.f;
    int bidx=-1;
    float mm=-3.0e38f;
    for(int f=0; f<n; f++){
        float4 r0=sf[4*f+0];
        float4 r1=sf[4*f+1];
        float4 r2=sf[4*f+2];
        float w0=fmaf(r0.z,py,fmaf(r0.y,px,r0.x));
        float w1=fmaf(r1.z,py,fmaf(r1.y,px,r1.x));
        float w2=fmaf(r2.z,py,fmaf(r2.y,px,r2.x));
        float mn=fminf(w0,fminf(w1,w2));
        mm=fmaxf(mm,mn);
        if(mn>=-1e-6f){
            float z=fmaf(r2.w,w2,fmaf(r1.w,w1,r0.w*w0));
            if(z>bz){ bz=z; bw0=w0; bw1=w1; bw2=w2; bidx=__float_as_int(sf[4*f+3].x); }
        }
    }
    float soft=1.0f/(1.0f+expf(-7000.0f*mm));
    int o=p*HW + y*IMW + x;
    g_soft[o]=soft;
    float f0=0.f, f1=0.f, f2=0.f;
    if(bidx>=0){
        const float* ff=&ffeat[bidx*9];
        f0=bw0*ff[0]+bw1*ff[3]+bw2*ff[6];
        f1=bw0*ff[1]+bw1*ff[4]+bw2*ff[7];
        f2=bw0*ff[2]+bw1*ff[5]+bw2*ff[8];
    }
    int base=p*3*HW + y*IMW + x;
    g_feats[base       ]=f0;
    g_feats[base+  HW  ]=f1;
    g_feats[base+2*HW  ]=f2;
}

// ---------------- erode (3x3 min, SAME, OOB=+inf) ----------------
__global__ void k_erode(){
    int idx=blockIdx.x*256+threadIdx.x;
    if(idx>=NPASS*HW) return;
    int p=idx/HW, rem=idx%HW, y=rem/IMW, x=rem%IMW;
    const float* s=&g_soft[p*HW];
    float m=3.4e38f;
    for(int dy=-1;dy<=1;dy++){
        int yy=y+dy; if(yy<0||yy>=IMH) continue;
        for(int dx=-1;dx<=1;dx++){
            int xx=x+dx; if(xx<0||xx>=IMW) continue;
            m=fminf(m, s[yy*IMW+xx]);
        }
    }
    g_mask[idx]=m;
}

// ---------------- blurs (reflect padding, 11-tap) ----------------
__device__ __forceinline__ float blurv_px(const float* img,int y,int x){
    float acc=0.f;
    #pragma unroll
    for(int k=0;k<11;k++){
        int yy=y+k-5;
        yy = yy<0 ? -yy : (yy>IMH-1 ? 2*(IMH-1)-yy : yy);
        acc += g_gauss[k]*img[yy*IMW+x];
    }
    return acc;
}
__device__ __forceinline__ float blurh_px(const float* img,int y,int x){
    float acc=0.f;
    #pragma unroll
    for(int k=0;k<11;k++){
        int xx=x+k-5;
        xx = xx<0 ? -xx : (xx>IMW-1 ? 2*(IMW-1)-xx : xx);
        acc += g_gauss[k]*img[y*IMW+xx];
    }
    return acc;
}

__global__ void k_blurv_rgb(){
    int idx=blockIdx.x*256+threadIdx.x;
    if(idx>=NPASS*3*HW) return;
    int img=idx/HW, rem=idx%HW;
    g_tmpA[idx]=blurv_px(&g_feats[img*HW], rem/IMW, rem%IMW);
}
__global__ void k_blurh_rgb(float* __restrict__ out){
    int idx=blockIdx.x*256+threadIdx.x;
    if(idx>=NPASS*3*HW) return;
    int img=idx/HW, rem=idx%HW;
    int p=img/3, c=img%3;
    out[(p*4+c)*HW+rem]=blurh_px(&g_tmpA[img*HW], rem/IMW, rem%IMW);
}
__global__ void k_blurv_m1(){
    int idx=blockIdx.x*256+threadIdx.x;
    if(idx>=NPASS*HW) return;
    int img=idx/HW, rem=idx%HW;
    g_tmpB[idx]=blurv_px(&g_mask[img*HW], rem/IMW, rem%IMW);
}
__global__ void k_blurh_m1(){
    int idx=blockIdx.x*256+threadIdx.x;
    if(idx>=NPASS*HW) return;
    int img=idx/HW, rem=idx%HW;
    g_tmpC[idx]=blurh_px(&g_tmpB[img*HW], rem/IMW, rem%IMW);
}
__global__ void k_blurv_m2(){
    int idx=blockIdx.x*256+threadIdx.x;
    if(idx>=NPASS*HW) return;
    int img=idx/HW, rem=idx%HW;
    g_tmpB[idx]=blurv_px(&g_tmpC[img*HW], rem/IMW, rem%IMW);
}
__global__ void k_blurh_m2(float* __restrict__ out){
    int idx=blockIdx.x*256+threadIdx.x;
    if(idx>=NPASS*HW) return;
    int img=idx/HW, rem=idx%HW;
    out[(img*4+3)*HW+rem]=blurh_px(&g_tmpB[img*HW], rem/IMW, rem%IMW);
}

// ---------------- launch ----------------
extern "C" void kernel_launch(void* const* d_in, const int* in_sizes, int n_in,
                              void* d_out, int out_size) {
    const float* trans=(const float*)d_in[0];
    const float* quat =(const float*)d_in[1];
    const float* uv   =(const float*)d_in[2];
    const float* ffeat=(const float*)d_in[3];
    const int*   faces=(const int*)  d_in[4];
    float* out=(float*)d_out;

    k_setup<<<1,32>>>(quat, trans);
    k_verts<<<NPASS, NVERT>>>(uv);
    k_faces<<<NPASS, NFACE>>>(faces);
    k_raster<<<dim3(10,10,NPASS), dim3(16,16)>>>(ffeat);
    k_erode<<<(NPASS*HW+255)/256, 256>>>();
    k_blurv_rgb<<<(NPASS*3*HW+255)/256, 256>>>();
    k_blurh_rgb<<<(NPASS*3*HW+255)/256, 256>>>(out);
    k_blurv_m1<<<(NPASS*HW+255)/256, 256>>>();
    k_blurh_m1<<<(NPASS*HW+255)/256, 256>>>();
    k_blurv_m2<<<(NPASS*HW+255)/256, 256>>>();
    k_blurh_m2<<<(NPASS*HW+255)/256, 256>>>(out);
}

// round 2
// speedup vs baseline: 1.9102x; 1.9102x over previous
#include <cuda_runtime.h>
#include <math.h>

#define NPASS 16
#define NVERT 642
#define NFACE 640
#define IMH 160
#define IMW 160
#define HW (IMH*IMW)
#define STEP (2.0f/159.0f)

// ---------------- scratch (device globals; no allocation) ----------------
__device__ float  g_R[NPASS*9];
__device__ float  g_toff[NPASS*3];
__device__ float  g_gauss[11];
__device__ float  g_focal;
__device__ float4 g_faceb[NPASS*NFACE*4];
__device__ int    g_nvalid[NPASS];
__device__ float  g_feats[NPASS*3*HW];
__device__ float  g_soft[NPASS*HW];
__device__ float  g_tmpC[NPASS*HW];

// ---------------- setup: rotations, offsets, constants ----------------
__device__ void quat_rod(const float* q, float scale, float* R){
    float w=q[0], x=q[1], y=q[2], z=q[3];
    float sn=sqrtf(x*x+y*y+z*z);
    float tt = 2.0f*((w<0.0f)? atan2f(-sn,-w) : atan2f(sn,w));
    float k = (sn>1e-8f)? (tt/fmaxf(sn,1e-8f)) : 2.0f;
    k *= scale;
    float ax=x*k, ay=y*k, az=z*k;
    float th=sqrtf(ax*ax+ay*ay+az*az);
    float inv=1.0f/fmaxf(th,1e-8f);
    float ux=ax*inv, uy=ay*inv, uz=az*inv;
    float s=sinf(th), c=cosf(th), cc=1.0f-c;
    R[0]=1.0f+cc*(-(uy*uy+uz*uz)); R[1]=-s*uz+cc*(ux*uy);          R[2]= s*uy+cc*(ux*uz);
    R[3]= s*uz+cc*(ux*uy);         R[4]=1.0f+cc*(-(ux*ux+uz*uz));  R[5]=-s*ux+cc*(uy*uz);
    R[6]=-s*uy+cc*(ux*uz);         R[7]= s*ux+cc*(uy*uz);          R[8]=1.0f+cc*(-(ux*ux+uy*uy));
}

__global__ void k_setup(const float* __restrict__ quat, const float* __restrict__ trans){
    if(threadIdx.x!=0 || blockIdx.x!=0) return;
    double s=0.0; double gg[11];
    for(int i=0;i<11;i++){ double xx=(double)(i-5); gg[i]=exp(-0.5*xx*xx); s+=gg[i]; }
    for(int i=0;i<11;i++) g_gauss[i]=(float)(gg[i]/s);
    g_focal=(float)(1.0/tan(1.57/4.0));
    for(int f=0; f<2; f++){
        float R[9], Rs[9];
        quat_rod(&quat[(f*2+1)*4], 1.0f, R);
        quat_rod(&quat[(f*2+0)*4], 1.0f/16.0f, Rs);
        for(int st=0; st<8; st++){
            int p=f*8+st;
            for(int i=0;i<9;i++) g_R[p*9+i]=R[i];
            float ti=(float)st*(1.0f/7.0f);
            for(int k=0;k<3;k++)
                g_toff[p*3+k]=trans[(f*2+1)*3+k] + ti*trans[(f*2+0)*3+k] - ((k==2)?2.0f:0.0f);
            float Rn[9];
            for(int i=0;i<3;i++)
                for(int j=0;j<3;j++)
                    Rn[i*3+j]=R[i*3+0]*Rs[0*3+j]+R[i*3+1]*Rs[1*3+j]+R[i*3+2]*Rs[2*3+j];
            for(int i=0;i<9;i++) R[i]=Rn[i];
        }
    }
}

// ---------------- verts + faces fused (one block per pass) ----------------
__global__ void __launch_bounds__(640) k_geom(const float* __restrict__ uv,
                                              const int* __restrict__ faces){
    int p=blockIdx.x; int i=threadIdx.x;
    __shared__ float sv[NVERT*3];
    __shared__ int wcnt[20], wbase[20];
    const float* R=&g_R[p*9];
    const float* t=&g_toff[p*3];
    for(int n=i; n<NVERT; n+=640){
        float ux=uv[n*3+0], uy=uv[n*3+1], uz=uv[n*3+2];
        sv[n*3+0]=R[0]*ux+R[1]*uy+R[2]*uz + t[0];
        sv[n*3+1]=R[3]*ux+R[4]*uy+R[5]*uz + t[1];
        sv[n*3+2]=R[6]*ux+R[7]*uy+R[8]*uz + t[2];
    }
    __syncthreads();
    int lane=i&31, wid=i>>5;
    int i0=faces[i*3+0], i1=faces[i*3+1], i2=faces[i*3+2];
    float ax3=sv[i0*3], ay3=sv[i0*3+1], az3=sv[i0*3+2];
    float bx3=sv[i1*3], by3=sv[i1*3+1], bz3=sv[i1*3+2];
    float cx3=sv[i2*3], cy3=sv[i2*3+1], cz3=sv[i2*3+2];
    float nz=(bx3-ax3)*(cy3-ay3)-(by3-ay3)*(cx3-ax3);
    float F=g_focal;
    float ax=(ax3*F)/(-az3), ay=(ay3*F)/(-az3);
    float bx=(bx3*F)/(-bz3), by=(by3*F)/(-bz3);
    float cx=(cx3*F)/(-cz3), cy=(cy3*F)/(-cz3);
    float denom=(bx-ax)*(cy-ay)-(by-ay)*(cx-ax);
    bool valid=(nz>0.0f)&&(fabsf(denom)>1e-9f);
    unsigned bal=__ballot_sync(0xffffffffu, valid);
    if(lane==0) wcnt[wid]=__popc(bal);
    __syncthreads();
    if(i==0){
        int acc=0;
        for(int w=0;w<20;w++){ wbase[w]=acc; acc+=wcnt[w]; }
        g_nvalid[p]=acc;
    }
    __syncthreads();
    if(valid){
        int pos=wbase[wid]+__popc(bal&((1u<<lane)-1u));
        float inv=1.0f/denom;
        float4* rec=&g_faceb[(p*NFACE+pos)*4];
        rec[0]=make_float4((bx*cy-by*cx)*inv, (by-cy)*inv, (cx-bx)*inv, az3);
        rec[1]=make_float4((cx*ay-cy*ax)*inv, (cy-ay)*inv, (ax-cx)*inv, bz3);
        rec[2]=make_float4((ax*by-ay*bx)*inv, (ay-by)*inv, (bx-ax)*inv, cz3);
        rec[3]=make_float4(__int_as_float(i), 0.f, 0.f, 0.f);
    }
}

// ---------------- rasterizer: 5 px/thread, band-culled faces ----------------
// block (32,8): covers 8 rows x 160 cols. thread x handles pixels x, x+32, ..., x+128
__global__ void __launch_bounds__(256) k_raster(const float* __restrict__ ffeat){
    int p=blockIdx.z;
    int y0=blockIdx.y*8;
    int tx=threadIdx.x;
    int y=y0+threadIdx.y;
    int tid=threadIdx.y*32+tx;
    int lane=tid&31, wid=tid>>5;

    __shared__ float4 s0[NFACE], s1[NFACE], s2[NFACE];
    __shared__ int   sid[NFACE];
    __shared__ int   warp_cnt[8], warp_off[8];
    __shared__ int   chunk_base;

    int n=g_nvalid[p];
    const float4* src=&g_faceb[p*NFACE*4];
    if(tid==0) chunk_base=0;
    __syncthreads();

    // band-cull parameters
    float pyc = 1.0f - ((float)y0+3.5f)*STEP;
    float pyr = 3.5f*STEP + 1e-4f;
    const float TAU = -0.002f;

    for(int base=0; base<n; base+=256){
        int f=base+tid;
        bool keep=false;
        float4 r0,r1,r2,r3;
        if(f<n){
            r0=src[4*f+0]; r1=src[4*f+1]; r2=src[4*f+2]; r3=src[4*f+3];
            // upper bound of min_k w_k over the band: min_k (A + |B|*1 + C*pyc + |C|*pyr)
            float u0=r0.x + fabsf(r0.y) + r0.z*pyc + fabsf(r0.z)*pyr;
            float u1=r1.x + fabsf(r1.y) + r1.z*pyc + fabsf(r1.z)*pyr;
            float u2=r2.x + fabsf(r2.y) + r2.z*pyc + fabsf(r2.z)*pyr;
            keep = fminf(u0,fminf(u1,u2)) >= TAU;
        }
        unsigned bal=__ballot_sync(0xffffffffu, keep);
        if(lane==0) warp_cnt[wid]=__popc(bal);
        __syncthreads();
        if(tid==0){
            int a=chunk_base;
            for(int w=0;w<8;w++){ warp_off[w]=a; a+=warp_cnt[w]; }
            chunk_base=a;
        }
        __syncthreads();
        if(keep){
            int pos=warp_off[wid]+__popc(bal&((1u<<lane)-1u));
            s0[pos]=r0; s1[pos]=r1; s2[pos]=r2; sid[pos]=__float_as_int(r3.x);
        }
        __syncthreads();
    }
    int m=chunk_base;

    float pyv = 1.0f - (float)y*STEP;
    float px0 = fmaf((float)tx, STEP, -1.0f);
    const float DX = 32.0f*STEP;

    float mm0=-3.0e38f, mm1=-3.0e38f, mm2=-3.0e38f, mm3=-3.0e38f, mm4=-3.0e38f;
    float bz0=-1e9f, bz1=-1e9f, bz2=-1e9f, bz3v=-1e9f, bz4=-1e9f;
    int   bi0=-1, bi1=-1, bi2=-1, bi3=-1, bi4=-1;

    for(int f=0; f<m; f++){
        float4 a=s0[f], b=s1[f], c=s2[f];
        float w0=fmaf(a.y,px0,fmaf(a.z,pyv,a.x));
        float w1=fmaf(b.y,px0,fmaf(b.z,pyv,b.x));
        float w2=fmaf(c.y,px0,fmaf(c.z,pyv,c.x));
        float d0=a.y*DX, d1=b.y*DX, d2=c.y*DX;
        #define PIX(MM,BZ,BI) { \
            float mn=fminf(w0,fminf(w1,w2)); \
            MM=fmaxf(MM,mn); \
            float z=fmaf(c.w,w2,fmaf(b.w,w1,a.w*w0)); \
            if(mn>=-1e-6f && z>BZ){ BZ=z; BI=f; } \
            w0+=d0; w1+=d1; w2+=d2; }
        PIX(mm0,bz0,bi0)
        PIX(mm1,bz1,bi1)
        PIX(mm2,bz2,bi2)
        PIX(mm3,bz3v,bi3)
        PIX(mm4,bz4,bi4)
        #undef PIX
    }

    float mms[5]={mm0,mm1,mm2,mm3,mm4};
    int   bis[5]={bi0,bi1,bi2,bi3,bi4};
    #pragma unroll
    for(int i=0;i<5;i++){
        int x=tx+32*i;
        float soft=1.0f/(1.0f+expf(-7000.0f*mms[i]));
        g_soft[p*HW + y*IMW + x]=soft;
        float f0=0.f,f1=0.f,f2=0.f;
        if(bis[i]>=0){
            float4 a=s0[bis[i]], b=s1[bis[i]], c=s2[bis[i]];
            float pxv=fmaf((float)x, STEP, -1.0f);
            float w0=fmaf(a.y,pxv,fmaf(a.z,pyv,a.x));
            float w1=fmaf(b.y,pxv,fmaf(b.z,pyv,b.x));
            float w2=fmaf(c.y,pxv,fmaf(c.z,pyv,c.x));
            const float* ff=&ffeat[sid[bis[i]]*9];
            f0=w0*ff[0]+w1*ff[3]+w2*ff[6];
            f1=w0*ff[1]+w1*ff[4]+w2*ff[7];
            f2=w0*ff[2]+w1*ff[5]+w2*ff[8];
        }
        int bo=p*3*HW + y*IMW + x;
        g_feats[bo      ]=f0;
        g_feats[bo+  HW ]=f1;
        g_feats[bo+2*HW ]=f2;
    }
}

// ---------------- fused separable blur (v+h) for RGB ----------------
// grid (10, 48): row-tile of 16 rows, image = p*3+c
__global__ void __launch_bounds__(256) k_blur_rgb(float* __restrict__ out){
    int tile=blockIdx.x, img=blockIdx.y;
    int y0=tile*16;
    const float* in=&g_feats[img*HW];
    __shared__ float sin_[26*160];
    __shared__ float sv[16*160];
    __shared__ float gk[11];
    int tid=threadIdx.x;
    if(tid<11) gk[tid]=g_gauss[tid];
    for(int idx=tid; idx<26*160; idx+=256){
        int r=idx/160, x=idx%160;
        int yy=y0-5+r;
        yy = yy<0 ? -yy : (yy>IMH-1 ? 2*(IMH-1)-yy : yy);
        sin_[idx]=in[yy*IMW+x];
    }
    __syncthreads();
    for(int idx=tid; idx<16*160; idx+=256){
        int j=idx/160, x=idx%160;
        float acc=0.f;
        #pragma unroll
        for(int k=0;k<11;k++) acc += gk[k]*sin_[(j+k)*160+x];
        sv[idx]=acc;
    }
    __syncthreads();
    int p=img/3, c=img%3;
    float* o=&out[(p*4+c)*HW];
    for(int idx=tid; idx<16*160; idx+=256){
        int j=idx/160, x=idx%160;
        float acc=0.f;
        #pragma unroll
        for(int k=0;k<11;k++){
            int xx=x+k-5;
            xx = xx<0 ? -xx : (xx>IMW-1 ? 2*(IMW-1)-xx : xx);
            acc += gk[k]*sv[j*160+xx];
        }
        o[(y0+j)*IMW+x]=acc;
    }
}

// ---------------- fused erode + first mask blur (v+h) ----------------
// grid (10, 16): row-tile of 16 rows, pass p
__global__ void __launch_bounds__(256) k_mask1(){
    int tile=blockIdx.x, p=blockIdx.y;
    int y0=tile*16;
    const float* in=&g_soft[p*HW];
    __shared__ float ss[28*160];   // soft rows y0-6..y0+21 (valid only)
    __shared__ float se[26*160];   // eroded rows y0-5..y0+20 (valid only)
    __shared__ float sv[16*160];
    __shared__ float gk[11];
    int tid=threadIdx.x;
    if(tid<11) gk[tid]=g_gauss[tid];
    for(int idx=tid; idx<28*160; idx+=256){
        int r=idx/160, x=idx%160;
        int yy=y0-6+r;
        if(yy>=0 && yy<IMH) ss[idx]=in[yy*IMW+x];
    }
    __syncthreads();
    // erode rows y0-5..y0+20 (valid rows only)
    for(int idx=tid; idx<26*160; idx+=256){
        int r=idx/160, x=idx%160;
        int yy=y0-5+r;
        if(yy<0 || yy>=IMH) continue;
        float mval=3.4e38f;
        #pragma unroll
        for(int dy=-1;dy<=1;dy++){
            int ry=yy+dy; if(ry<0||ry>=IMH) continue;
            int sr=ry-(y0-6);
            #pragma unroll
            for(int dx=-1;dx<=1;dx++){
                int xx=x+dx; if(xx<0||xx>=IMW) continue;
                mval=fminf(mval, ss[sr*160+xx]);
            }
        }
        se[idx]=mval;
    }
    __syncthreads();
    // vertical blur on eroded, rows y0..y0+15 (reflect at image boundary)
    for(int idx=tid; idx<16*160; idx+=256){
        int j=idx/160, x=idx%160;
        int yb=y0+j;
        float acc=0.f;
        #pragma unroll
        for(int k=0;k<11;k++){
            int yy=yb+k-5;
            yy = yy<0 ? -yy : (yy>IMH-1 ? 2*(IMH-1)-yy : yy);
            acc += gk[k]*se[(yy-(y0-5))*160+x];
        }
        sv[idx]=acc;
    }
    __syncthreads();
    float* o=&g_tmpC[p*HW];
    for(int idx=tid; idx<16*160; idx+=256){
        int j=idx/160, x=idx%160;
        float acc=0.f;
        #pragma unroll
        for(int k=0;k<11;k++){
            int xx=x+k-5;
            xx = xx<0 ? -xx : (xx>IMW-1 ? 2*(IMW-1)-xx : xx);
            acc += gk[k]*sv[j*160+xx];
        }
        o[(y0+j)*IMW+x]=acc;
    }
}

// ---------------- second mask blur (v+h) -> out channel 3 ----------------
__global__ void __launch_bounds__(256) k_mask2(float* __restrict__ out){
    int tile=blockIdx.x, p=blockIdx.y;
    int y0=tile*16;
    const float* in=&g_tmpC[p*HW];
    __shared__ float sin_[26*160];
    __shared__ float sv[16*160];
    __shared__ float gk[11];
    int tid=threadIdx.x;
    if(tid<11) gk[tid]=g_gauss[tid];
    for(int idx=tid; idx<26*160; idx+=256){
        int r=idx/160, x=idx%160;
        int yy=y0-5+r;
        yy = yy<0 ? -yy : (yy>IMH-1 ? 2*(IMH-1)-yy : yy);
        sin_[idx]=in[yy*IMW+x];
    }
    __syncthreads();
    for(int idx=tid; idx<16*160; idx+=256){
        int j=idx/160, x=idx%160;
        float acc=0.f;
        #pragma unroll
        for(int k=0;k<11;k++) acc += gk[k]*sin_[(j+k)*160+x];
        sv[idx]=acc;
    }
    __syncthreads();
    float* o=&out[(p*4+3)*HW];
    for(int idx=tid; idx<16*160; idx+=256){
        int j=idx/160, x=idx%160;
        float acc=0.f;
        #pragma unroll
        for(int k=0;k<11;k++){
            int xx=x+k-5;
            xx = xx<0 ? -xx : (xx>IMW-1 ? 2*(IMW-1)-xx : xx);
            acc += gk[k]*sv[j*160+xx];
        }
        o[(y0+j)*IMW+x]=acc;
    }
}

// ---------------- launch ----------------
extern "C" void kernel_launch(void* const* d_in, const int* in_sizes, int n_in,
                              void* d_out, int out_size) {
    const float* trans=(const float*)d_in[0];
    const float* quat =(const float*)d_in[1];
    const float* uv   =(const float*)d_in[2];
    const float* ffeat=(const float*)d_in[3];
    const int*   faces=(const int*)  d_in[4];
    float* out=(float*)d_out;

    k_setup<<<1,32>>>(quat, trans);
    k_geom<<<NPASS, 640>>>(uv, faces);
    k_raster<<<dim3(1,20,NPASS), dim3(32,8)>>>(ffeat);
    k_blur_rgb<<<dim3(10,48), 256>>>(out);
    k_mask1<<<dim3(10,NPASS), 256>>>();
    k_mask2<<<dim3(10,NPASS), 256>>>(out);
}

// round 6
// speedup vs baseline: 2.1761x; 1.1392x over previous
#include <cuda_runtime.h>
#include <math.h>

#define NPASS 16
#define NVERT 642
#define NFACE 640
#define IMH 160
#define IMW 160
#define HW (IMH*IMW)
#define STEP (2.0f/159.0f)

// gaussian 11-tap weights (fp64 exp/normalize, rounded to float)
#define G0 1.4867195e-06f
#define G1 1.3383023e-04f
#define G2 4.4318484e-03f
#define G3 5.3990966e-02f
#define G4 2.4197073e-01f
#define G5 3.9894228e-01f
__device__ __constant__ float c_gauss[11]={G0,G1,G2,G3,G4,G5,G4,G3,G2,G1,G0};

// ---------------- scratch ----------------
__device__ float4 g_faceb[NPASS*NFACE*4];
__device__ int    g_nvalid[NPASS];
__device__ float  g_feats[NPASS*3*HW];
__device__ float  g_soft[NPASS*HW];

// ---------------- helpers ----------------
__device__ void quat_rod(const float* q, float scale, float* R){
    float w=q[0], x=q[1], y=q[2], z=q[3];
    float sn=sqrtf(x*x+y*y+z*z);
    float tt = 2.0f*((w<0.0f)? atan2f(-sn,-w) : atan2f(sn,w));
    float k = (sn>1e-8f)? (tt/fmaxf(sn,1e-8f)) : 2.0f;
    k *= scale;
    float ax=x*k, ay=y*k, az=z*k;
    float th=sqrtf(ax*ax+ay*ay+az*az);
    float inv=1.0f/fmaxf(th,1e-8f);
    float ux=ax*inv, uy=ay*inv, uz=az*inv;
    float s=sinf(th), c=cosf(th), cc=1.0f-c;
    R[0]=1.0f+cc*(-(uy*uy+uz*uz)); R[1]=-s*uz+cc*(ux*uy);          R[2]= s*uy+cc*(ux*uz);
    R[3]= s*uz+cc*(ux*uy);         R[4]=1.0f+cc*(-(ux*ux+uz*uz));  R[5]=-s*ux+cc*(uy*uz);
    R[6]=-s*uy+cc*(ux*uz);         R[7]= s*ux+cc*(uy*uz);          R[8]=1.0f+cc*(-(ux*ux+uy*uy));
}

// ---------------- geometry: setup + verts + face records (1 block/pass) ----------------
__global__ void __launch_bounds__(640) k_geom(const float* __restrict__ uv,
                                              const int* __restrict__ faces,
                                              const float* __restrict__ quat,
                                              const float* __restrict__ trans){
    int p=blockIdx.x; int i=threadIdx.x;
    __shared__ float sR[9], sT[3];
    __shared__ float sv[NVERT*3];
    __shared__ int wcnt[20], wbase[20];
    if(i==0){
        int f=p>>3, st=p&7;
        float R[9], Rs[9];
        quat_rod(&quat[(f*2+1)*4], 1.0f, R);
        quat_rod(&quat[(f*2+0)*4], 1.0f/16.0f, Rs);
        for(int s=0;s<st;s++){
            float Rn[9];
            for(int a=0;a<3;a++)
                for(int b=0;b<3;b++)
                    Rn[a*3+b]=R[a*3+0]*Rs[0*3+b]+R[a*3+1]*Rs[1*3+b]+R[a*3+2]*Rs[2*3+b];
            for(int k=0;k<9;k++) R[k]=Rn[k];
        }
        for(int k=0;k<9;k++) sR[k]=R[k];
        float ti=(float)st*(1.0f/7.0f);
        for(int k=0;k<3;k++)
            sT[k]=trans[(f*2+1)*3+k] + ti*trans[(f*2+0)*3+k] - ((k==2)?2.0f:0.0f);
    }
    __syncthreads();
    for(int n=i; n<NVERT; n+=640){
        float ux=uv[n*3+0], uy=uv[n*3+1], uz=uv[n*3+2];
        sv[n*3+0]=sR[0]*ux+sR[1]*uy+sR[2]*uz + sT[0];
        sv[n*3+1]=sR[3]*ux+sR[4]*uy+sR[5]*uz + sT[1];
        sv[n*3+2]=sR[6]*ux+sR[7]*uy+sR[8]*uz + sT[2];
    }
    __syncthreads();
    int lane=i&31, wid=i>>5;
    int i0=faces[i*3+0], i1=faces[i*3+1], i2=faces[i*3+2];
    float ax3=sv[i0*3], ay3=sv[i0*3+1], az3=sv[i0*3+2];
    float bx3=sv[i1*3], by3=sv[i1*3+1], bz3=sv[i1*3+2];
    float cx3=sv[i2*3], cy3=sv[i2*3+1], cz3=sv[i2*3+2];
    float nz=(bx3-ax3)*(cy3-ay3)-(by3-ay3)*(cx3-ax3);
    // focal: EXACT reference value 1/tan(1.57/4) computed in double (NOT pi/8!)
    const float F=(float)(1.0/tan(1.57/4.0));
    float ax=(ax3*F)/(-az3), ay=(ay3*F)/(-az3);
    float bx=(bx3*F)/(-bz3), by=(by3*F)/(-bz3);
    float cx=(cx3*F)/(-cz3), cy=(cy3*F)/(-cz3);
    float denom=(bx-ax)*(cy-ay)-(by-ay)*(cx-ax);
    bool valid=(nz>0.0f)&&(fabsf(denom)>1e-9f);
    unsigned bal=__ballot_sync(0xffffffffu, valid);
    if(lane==0) wcnt[wid]=__popc(bal);
    __syncthreads();
    if(i==0){
        int acc=0;
        for(int w=0;w<20;w++){ wbase[w]=acc; acc+=wcnt[w]; }
        g_nvalid[p]=acc;
    }
    __syncthreads();
    if(valid){
        int pos=wbase[wid]+__popc(bal&((1u<<lane)-1u));
        float inv=1.0f/denom;
        float4* rec=&g_faceb[(p*NFACE+pos)*4];
        rec[0]=make_float4((bx*cy-by*cx)*inv, (by-cy)*inv, (cx-bx)*inv, az3);
        rec[1]=make_float4((cx*ay-cy*ax)*inv, (cy-ay)*inv, (ax-cx)*inv, bz3);
        rec[2]=make_float4((ax*by-ay*bx)*inv, (ay-by)*inv, (bx-ax)*inv, cz3);
        rec[3]=make_float4(__int_as_float(i), 0.f, 0.f, 0.f);
    }
}

// ---------------- rasterizer: 5 px/thread, band-culled faces ----------------
// block (32,8): covers 8 rows x 160 cols. thread x handles pixels x, x+32, ..., x+128
__global__ void __launch_bounds__(256) k_raster(const float* __restrict__ ffeat){
    int p=blockIdx.z;
    int y0=blockIdx.y*8;
    int tx=threadIdx.x;
    int y=y0+threadIdx.y;
    int tid=threadIdx.y*32+tx;
    int lane=tid&31, wid=tid>>5;

    __shared__ float4 s0[NFACE], s1[NFACE], s2[NFACE];
    __shared__ int   sid[NFACE];
    __shared__ int   warp_cnt[8], warp_off[8];
    __shared__ int   chunk_base;

    int n=g_nvalid[p];
    const float4* src=&g_faceb[p*NFACE*4];
    if(tid==0) chunk_base=0;
    __syncthreads();

    float pyc = 1.0f - ((float)y0+3.5f)*STEP;
    float pyr = 3.5f*STEP + 1e-4f;
    const float TAU = -0.002f;

    for(int base=0; base<n; base+=256){
        int f=base+tid;
        bool keep=false;
        float4 r0,r1,r2,r3;
        if(f<n){
            r0=src[4*f+0]; r1=src[4*f+1]; r2=src[4*f+2]; r3=src[4*f+3];
            float u0=r0.x + fabsf(r0.y) + r0.z*pyc + fabsf(r0.z)*pyr;
            float u1=r1.x + fabsf(r1.y) + r1.z*pyc + fabsf(r1.z)*pyr;
            float u2=r2.x + fabsf(r2.y) + r2.z*pyc + fabsf(r2.z)*pyr;
            keep = fminf(u0,fminf(u1,u2)) >= TAU;
        }
        unsigned bal=__ballot_sync(0xffffffffu, keep);
        if(lane==0) warp_cnt[wid]=__popc(bal);
        __syncthreads();
        if(tid==0){
            int a=chunk_base;
            for(int w=0;w<8;w++){ warp_off[w]=a; a+=warp_cnt[w]; }
            chunk_base=a;
        }
        __syncthreads();
        if(keep){
            int pos=warp_off[wid]+__popc(bal&((1u<<lane)-1u));
            s0[pos]=r0; s1[pos]=r1; s2[pos]=r2; sid[pos]=__float_as_int(r3.x);
        }
        __syncthreads();
    }
    int m=chunk_base;

    float pyv = 1.0f - (float)y*STEP;
    float px0 = fmaf((float)tx, STEP, -1.0f);
    const float DX = 32.0f*STEP;

    float mm0=-3.0e38f, mm1=-3.0e38f, mm2=-3.0e38f, mm3=-3.0e38f, mm4=-3.0e38f;
    float bz0=-1e9f, bz1=-1e9f, bz2=-1e9f, bz3v=-1e9f, bz4=-1e9f;
    int   bi0=-1, bi1=-1, bi2=-1, bi3=-1, bi4=-1;

    for(int f=0; f<m; f++){
        float4 a=s0[f], b=s1[f], c=s2[f];
        float w0=fmaf(a.y,px0,fmaf(a.z,pyv,a.x));
        float w1=fmaf(b.y,px0,fmaf(b.z,pyv,b.x));
        float w2=fmaf(c.y,px0,fmaf(c.z,pyv,c.x));
        float d0=a.y*DX, d1=b.y*DX, d2=c.y*DX;
        #define PIX(MM,BZ,BI) { \
            float mn=fminf(w0,fminf(w1,w2)); \
            MM=fmaxf(MM,mn); \
            float z=fmaf(c.w,w2,fmaf(b.w,w1,a.w*w0)); \
            if(mn>=-1e-6f && z>BZ){ BZ=z; BI=f; } \
            w0+=d0; w1+=d1; w2+=d2; }
        PIX(mm0,bz0,bi0)
        PIX(mm1,bz1,bi1)
        PIX(mm2,bz2,bi2)
        PIX(mm3,bz3v,bi3)
        PIX(mm4,bz4,bi4)
        #undef PIX
    }

    float mms[5]={mm0,mm1,mm2,mm3,mm4};
    int   bis[5]={bi0,bi1,bi2,bi3,bi4};
    #pragma unroll
    for(int i=0;i<5;i++){
        int x=tx+32*i;
        float soft=1.0f/(1.0f+expf(-7000.0f*mms[i]));
        g_soft[p*HW + y*IMW + x]=soft;
        float f0=0.f,f1=0.f,f2=0.f;
        if(bis[i]>=0){
            float4 a=s0[bis[i]], b=s1[bis[i]], c=s2[bis[i]];
            float pxv=fmaf((float)x, STEP, -1.0f);
            float w0=fmaf(a.y,pxv,fmaf(a.z,pyv,a.x));
            float w1=fmaf(b.y,pxv,fmaf(b.z,pyv,b.x));
            float w2=fmaf(c.y,pxv,fmaf(c.z,pyv,c.x));
            const float* ff=&ffeat[sid[bis[i]]*9];
            f0=w0*ff[0]+w1*ff[3]+w2*ff[6];
            f1=w0*ff[1]+w1*ff[4]+w2*ff[7];
            f2=w0*ff[2]+w1*ff[5]+w2*ff[8];
        }
        int bo=p*3*HW + y*IMW + x;
        g_feats[bo      ]=f0;
        g_feats[bo+  HW ]=f1;
        g_feats[bo+2*HW ]=f2;
    }
}

// ---------------- fused post: RGB blur OR mask chain, per 16-row tile ----------------
// grid (10, 64): blockIdx.y<48 -> rgb image (p*3+c), else mask pass (y-48)
__global__ void __launch_bounds__(256) k_post(float* __restrict__ out){
    __shared__ float bufA[38*160];
    __shared__ float bufB[36*160];
    int tile=blockIdx.x, task=blockIdx.y;
    int y0=tile*16;
    int tid=threadIdx.x;

    if(task<48){
        // ---- RGB separable blur ----
        const float* in=&g_feats[task*HW];
        for(int idx=tid; idx<26*160; idx+=256){
            int r=idx/160, x=idx%160;
            int yy=y0-5+r;
            yy = yy<0 ? -yy : (yy>IMH-1 ? 2*(IMH-1)-yy : yy);
            bufA[idx]=in[yy*IMW+x];
        }
        __syncthreads();
        for(int idx=tid; idx<16*160; idx+=256){
            int j=idx/160, x=idx%160;
            float acc=0.f;
            #pragma unroll
            for(int k=0;k<11;k++) acc += c_gauss[k]*bufA[(j+k)*160+x];
            bufB[idx]=acc;
        }
        __syncthreads();
        int p=task/3, c=task%3;
        float* o=&out[(p*4+c)*HW];
        for(int idx=tid; idx<16*160; idx+=256){
            int j=idx/160, x=idx%160;
            float acc=0.f;
            #pragma unroll
            for(int k=0;k<11;k++){
                int xx=x+k-5;
                xx = xx<0 ? -xx : (xx>IMW-1 ? 2*(IMW-1)-xx : xx);
                acc += c_gauss[k]*bufB[j*160+xx];
            }
            o[(y0+j)*IMW+x]=acc;
        }
    } else {
        // ---- mask chain: erode -> blurV -> blurH -> blurV -> blurH ----
        int p=task-48;
        const float* in=&g_soft[p*HW];
        // 1. load soft rows [y0-11, y0+26] (valid only) into bufA (base y0-11)
        for(int idx=tid; idx<38*160; idx+=256){
            int r=idx/160, x=idx%160;
            int yy=y0-11+r;
            if(yy>=0 && yy<IMH) bufA[idx]=in[yy*IMW+x];
        }
        __syncthreads();
        // 2. erode rows [y0-10, y0+25] (valid only) into bufB (base y0-10)
        for(int idx=tid; idx<36*160; idx+=256){
            int r=idx/160, x=idx%160;
            int yy=y0-10+r;
            if(yy<0 || yy>=IMH) continue;
            float mval=3.4e38f;
            #pragma unroll
            for(int dy=-1;dy<=1;dy++){
                int ry=yy+dy; if(ry<0||ry>=IMH) continue;
                int sr=ry-(y0-11);
                #pragma unroll
                for(int dx=-1;dx<=1;dx++){
                    int xx=x+dx; if(xx<0||xx>=IMW) continue;
                    mval=fminf(mval, bufA[sr*160+xx]);
                }
            }
            bufB[idx]=mval;
        }
        __syncthreads();
        // 3. blurV1 rows [y0-5, y0+20] (valid only) into bufA (base y0-5)
        for(int idx=tid; idx<26*160; idx+=256){
            int r=idx/160, x=idx%160;
            int yb=y0-5+r;
            if(yb<0 || yb>=IMH) continue;
            float acc=0.f;
            #pragma unroll
            for(int k=0;k<11;k++){
                int yy=yb+k-5;
                yy = yy<0 ? -yy : (yy>IMH-1 ? 2*(IMH-1)-yy : yy);
                acc += c_gauss[k]*bufB[(yy-(y0-10))*160+x];
            }
            bufA[idx]=acc;
        }
        __syncthreads();
        // 4. blurH1 rows [y0-5, y0+20] (valid only) into bufB (base y0-5)
        for(int idx=tid; idx<26*160; idx+=256){
            int r=idx/160, x=idx%160;
            int yb=y0-5+r;
            if(yb<0 || yb>=IMH) continue;
            float acc=0.f;
            #pragma unroll
            for(int k=0;k<11;k++){
                int xx=x+k-5;
                xx = xx<0 ? -xx : (xx>IMW-1 ? 2*(IMW-1)-xx : xx);
                acc += c_gauss[k]*bufA[r*160+xx];
            }
            bufB[idx]=acc;
        }
        __syncthreads();
        // 5. blurV2 rows [y0, y0+15] into bufA (base y0)
        for(int idx=tid; idx<16*160; idx+=256){
            int j=idx/160, x=idx%160;
            int yb=y0+j;
            float acc=0.f;
            #pragma unroll
            for(int k=0;k<11;k++){
                int yy=yb+k-5;
                yy = yy<0 ? -yy : (yy>IMH-1 ? 2*(IMH-1)-yy : yy);
                acc += c_gauss[k]*bufB[(yy-(y0-5))*160+x];
            }
            bufA[idx]=acc;
        }
        __syncthreads();
        // 6. blurH2 rows [y0, y0+15] -> out channel 3
        float* o=&out[(p*4+3)*HW];
        for(int idx=tid; idx<16*160; idx+=256){
            int j=idx/160, x=idx%160;
            float acc=0.f;
            #pragma unroll
            for(int k=0;k<11;k++){
                int xx=x+k-5;
                xx = xx<0 ? -xx : (xx>IMW-1 ? 2*(IMW-1)-xx : xx);
                acc += c_gauss[k]*bufA[j*160+xx];
            }
            o[(y0+j)*IMW+x]=acc;
        }
    }
}

// ---------------- launch ----------------
extern "C" void kernel_launch(void* const* d_in, const int* in_sizes, int n_in,
                              void* d_out, int out_size) {
    const float* trans=(const float*)d_in[0];
    const float* quat =(const float*)d_in[1];
    const float* uv   =(const float*)d_in[2];
    const float* ffeat=(const float*)d_in[3];
    const int*   faces=(const int*)  d_in[4];
    float* out=(float*)d_out;

    k_geom<<<NPASS, 640>>>(uv, faces, quat, trans);
    k_raster<<<dim3(1,20,NPASS), dim3(32,8)>>>(ffeat);
    k_post<<<dim3(10,64), 256>>>(out);
}

// round 7
// speedup vs baseline: 2.2651x; 1.0409x over previous
#include <cuda_runtime.h>
#include <math.h>

#define NPASS 16
#define NFACE 640
#define NVERT 642
#define IMH 160
#define IMW 160
#define HW (IMH*IMW)
#define STEP (2.0f/159.0f)
#define GRID_ALL 320

// gaussian 11-tap weights (fp64 exp/normalize, rounded to float)
#define G0 1.4867195e-06f
#define G1 1.3383023e-04f
#define G2 4.4318484e-03f
#define G3 5.3990966e-02f
#define G4 2.4197073e-01f
#define G5 3.9894228e-01f
__device__ __constant__ float c_gauss[11]={G0,G1,G2,G3,G4,G5,G4,G3,G2,G1,G0};

// ---------------- scratch ----------------
__device__ float4 g_faceb[NPASS*NFACE*4];   // fallback path only
__device__ int    g_nvalid[NPASS];          // fallback path only
__device__ float  g_feats[NPASS*3*HW];
__device__ float  g_soft[NPASS*HW];
__device__ unsigned g_count = 0;            // persistent grid-barrier ticket

// ---------------- helpers ----------------
__device__ void quat_rod(const float* q, float scale, float* R){
    float w=q[0], x=q[1], y=q[2], z=q[3];
    float sn=sqrtf(x*x+y*y+z*z);
    float tt = 2.0f*((w<0.0f)? atan2f(-sn,-w) : atan2f(sn,w));
    float k = (sn>1e-8f)? (tt/fmaxf(sn,1e-8f)) : 2.0f;
    k *= scale;
    float ax=x*k, ay=y*k, az=z*k;
    float th=sqrtf(ax*ax+ay*ay+az*az);
    float inv=1.0f/fmaxf(th,1e-8f);
    float ux=ax*inv, uy=ay*inv, uz=az*inv;
    float s=sinf(th), c=cosf(th), cc=1.0f-c;
    R[0]=1.0f+cc*(-(uy*uy+uz*uz)); R[1]=-s*uz+cc*(ux*uy);          R[2]= s*uy+cc*(ux*uz);
    R[3]= s*uz+cc*(ux*uy);         R[4]=1.0f+cc*(-(ux*ux+uz*uz));  R[5]=-s*ux+cc*(uy*uz);
    R[6]=-s*uy+cc*(ux*uz);         R[7]= s*ux+cc*(uy*uz);          R[8]=1.0f+cc*(-(ux*ux+uy*uy));
}

// rotation chain + translation for pass p (serial, call from one thread)
__device__ void compute_RT(int p, const float* quat, const float* trans,
                           float* sR, float* sT){
    int f=p>>3, st=p&7;
    float R[9], Rs[9];
    quat_rod(&quat[(f*2+1)*4], 1.0f, R);
    quat_rod(&quat[(f*2+0)*4], 1.0f/16.0f, Rs);
    for(int s=0;s<st;s++){
        float Rn[9];
        for(int a=0;a<3;a++)
            for(int b=0;b<3;b++)
                Rn[a*3+b]=R[a*3+0]*Rs[0*3+b]+R[a*3+1]*Rs[1*3+b]+R[a*3+2]*Rs[2*3+b];
        for(int k=0;k<9;k++) R[k]=Rn[k];
    }
    for(int k=0;k<9;k++) sR[k]=R[k];
    float ti=(float)st*(1.0f/7.0f);
    for(int k=0;k<3;k++)
        sT[k]=trans[(f*2+1)*3+k] + ti*trans[(f*2+0)*3+k] - ((k==2)?2.0f:0.0f);
}

// face record from smem verts; returns valid
__device__ __forceinline__ bool face_record(const float* sv, const int* faces, int i,
                                            float4& r0, float4& r1, float4& r2){
    int i0=faces[i*3+0], i1=faces[i*3+1], i2=faces[i*3+2];
    float ax3=sv[i0*3], ay3=sv[i0*3+1], az3=sv[i0*3+2];
    float bx3=sv[i1*3], by3=sv[i1*3+1], bz3=sv[i1*3+2];
    float cx3=sv[i2*3], cy3=sv[i2*3+1], cz3=sv[i2*3+2];
    float nz=(bx3-ax3)*(cy3-ay3)-(by3-ay3)*(cx3-ax3);
    const float F=(float)(1.0/tan(1.57/4.0));   // exact reference focal (NOT pi/8)
    float ax=(ax3*F)/(-az3), ay=(ay3*F)/(-az3);
    float bx=(bx3*F)/(-bz3), by=(by3*F)/(-bz3);
    float cx=(cx3*F)/(-cz3), cy=(cy3*F)/(-cz3);
    float denom=(bx-ax)*(cy-ay)-(by-ay)*(cx-ax);
    bool valid=(nz>0.0f)&&(fabsf(denom)>1e-9f);
    if(valid){
        float inv=1.0f/denom;
        r0=make_float4((bx*cy-by*cx)*inv, (by-cy)*inv, (cx-bx)*inv, az3);
        r1=make_float4((cx*ay-cy*ax)*inv, (cy-ay)*inv, (ax-cx)*inv, bz3);
        r2=make_float4((ax*by-ay*bx)*inv, (ay-by)*inv, (bx-ax)*inv, cz3);
    }
    return valid;
}

// ---------------- shared post-task (rgb blur or mask chain, one 16-row tile) ----------------
// bufA >= 38*160 floats, bufB >= 36*160 floats
__device__ void post_task(float* bufA, float* bufB, int task, int tile,
                          float* __restrict__ out, int tid){
    int y0=tile*16;
    if(task<48){
        const float* in=&g_feats[task*HW];
        for(int idx=tid; idx<26*160; idx+=256){
            int r=idx/160, x=idx%160;
            int yy=y0-5+r;
            yy = yy<0 ? -yy : (yy>IMH-1 ? 2*(IMH-1)-yy : yy);
            bufA[idx]=in[yy*IMW+x];
        }
        __syncthreads();
        for(int idx=tid; idx<16*160; idx+=256){
            int j=idx/160, x=idx%160;
            float acc=0.f;
            #pragma unroll
            for(int k=0;k<11;k++) acc += c_gauss[k]*bufA[(j+k)*160+x];
            bufB[idx]=acc;
        }
        __syncthreads();
        int p=task/3, c=task%3;
        float* o=&out[(p*4+c)*HW];
        for(int idx=tid; idx<16*160; idx+=256){
            int j=idx/160, x=idx%160;
            float acc=0.f;
            #pragma unroll
            for(int k=0;k<11;k++){
                int xx=x+k-5;
                xx = xx<0 ? -xx : (xx>IMW-1 ? 2*(IMW-1)-xx : xx);
                acc += c_gauss[k]*bufB[j*160+xx];
            }
            o[(y0+j)*IMW+x]=acc;
        }
    } else {
        int p=task-48;
        const float* in=&g_soft[p*HW];
        for(int idx=tid; idx<38*160; idx+=256){
            int r=idx/160, x=idx%160;
            int yy=y0-11+r;
            if(yy>=0 && yy<IMH) bufA[idx]=in[yy*IMW+x];
        }
        __syncthreads();
        for(int idx=tid; idx<36*160; idx+=256){
            int r=idx/160, x=idx%160;
            int yy=y0-10+r;
            if(yy<0 || yy>=IMH) continue;
            float mval=3.4e38f;
            #pragma unroll
            for(int dy=-1;dy<=1;dy++){
                int ry=yy+dy; if(ry<0||ry>=IMH) continue;
                int sr=ry-(y0-11);
                #pragma unroll
                for(int dx=-1;dx<=1;dx++){
                    int xx=x+dx; if(xx<0||xx>=IMW) continue;
                    mval=fminf(mval, bufA[sr*160+xx]);
                }
            }
            bufB[idx]=mval;
        }
        __syncthreads();
        for(int idx=tid; idx<26*160; idx+=256){
            int r=idx/160, x=idx%160;
            int yb=y0-5+r;
            if(yb<0 || yb>=IMH) continue;
            float acc=0.f;
            #pragma unroll
            for(int k=0;k<11;k++){
                int yy=yb+k-5;
                yy = yy<0 ? -yy : (yy>IMH-1 ? 2*(IMH-1)-yy : yy);
                acc += c_gauss[k]*bufB[(yy-(y0-10))*160+x];
            }
            bufA[idx]=acc;
        }
        __syncthreads();
        for(int idx=tid; idx<26*160; idx+=256){
            int r=idx/160, x=idx%160;
            int yb=y0-5+r;
            if(yb<0 || yb>=IMH) continue;
            float acc=0.f;
            #pragma unroll
            for(int k=0;k<11;k++){
                int xx=x+k-5;
                xx = xx<0 ? -xx : (xx>IMW-1 ? 2*(IMW-1)-xx : xx);
                acc += c_gauss[k]*bufA[r*160+xx];
            }
            bufB[idx]=acc;
        }
        __syncthreads();
        for(int idx=tid; idx<16*160; idx+=256){
            int j=idx/160, x=idx%160;
            int yb=y0+j;
            float acc=0.f;
            #pragma unroll
            for(int k=0;k<11;k++){
                int yy=yb+k-5;
                yy = yy<0 ? -yy : (yy>IMH-1 ? 2*(IMH-1)-yy : yy);
                acc += c_gauss[k]*bufB[(yy-(y0-5))*160+x];
            }
            bufA[idx]=acc;
        }
        __syncthreads();
        float* o=&out[(p*4+3)*HW];
        for(int idx=tid; idx<16*160; idx+=256){
            int j=idx/160, x=idx%160;
            float acc=0.f;
            #pragma unroll
            for(int k=0;k<11;k++){
                int xx=x+k-5;
                xx = xx<0 ? -xx : (xx>IMW-1 ? 2*(IMW-1)-xx : xx);
                acc += c_gauss[k]*bufA[j*160+xx];
            }
            o[(y0+j)*IMW+x]=acc;
        }
    }
}

// ---------------- shared raster pixel-loop ----------------
__device__ void raster_pixels(const float4* s0, const float4* s1, const float4* s2,
                              const int* sid, int m, int p, int y0, int tx, int ty,
                              const float* __restrict__ ffeat){
    int y=y0+ty;
    float pyv = 1.0f - (float)y*STEP;
    float px0 = fmaf((float)tx, STEP, -1.0f);
    const float DX = 32.0f*STEP;

    float mm0=-3.0e38f, mm1=-3.0e38f, mm2=-3.0e38f, mm3=-3.0e38f, mm4=-3.0e38f;
    float bz0=-1e9f, bz1=-1e9f, bz2=-1e9f, bz3v=-1e9f, bz4=-1e9f;
    int   bi0=-1, bi1=-1, bi2=-1, bi3=-1, bi4=-1;

    for(int f=0; f<m; f++){
        float4 a=s0[f], b=s1[f], c=s2[f];
        float w0=fmaf(a.y,px0,fmaf(a.z,pyv,a.x));
        float w1=fmaf(b.y,px0,fmaf(b.z,pyv,b.x));
        float w2=fmaf(c.y,px0,fmaf(c.z,pyv,c.x));
        float d0=a.y*DX, d1=b.y*DX, d2=c.y*DX;
        #define PIX(MM,BZ,BI) { \
            float mn=fminf(w0,fminf(w1,w2)); \
            MM=fmaxf(MM,mn); \
            float z=fmaf(c.w,w2,fmaf(b.w,w1,a.w*w0)); \
            if(mn>=-1e-6f && z>BZ){ BZ=z; BI=f; } \
            w0+=d0; w1+=d1; w2+=d2; }
        PIX(mm0,bz0,bi0)
        PIX(mm1,bz1,bi1)
        PIX(mm2,bz2,bi2)
        PIX(mm3,bz3v,bi3)
        PIX(mm4,bz4,bi4)
        #undef PIX
    }

    float mms[5]={mm0,mm1,mm2,mm3,mm4};
    int   bis[5]={bi0,bi1,bi2,bi3,bi4};
    #pragma unroll
    for(int i=0;i<5;i++){
        int x=tx+32*i;
        float soft=1.0f/(1.0f+expf(-7000.0f*mms[i]));
        g_soft[p*HW + y*IMW + x]=soft;
        float f0=0.f,f1=0.f,f2=0.f;
        if(bis[i]>=0){
            float4 a=s0[bis[i]], b=s1[bis[i]], c=s2[bis[i]];
            float pxv=fmaf((float)x, STEP, -1.0f);
            float w0=fmaf(a.y,pxv,fmaf(a.z,pyv,a.x));
            float w1=fmaf(b.y,pxv,fmaf(b.z,pyv,b.x));
            float w2=fmaf(c.y,pxv,fmaf(c.z,pyv,c.x));
            const float* ff=&ffeat[sid[bis[i]]*9];
            f0=w0*ff[0]+w1*ff[3]+w2*ff[6];
            f1=w0*ff[1]+w1*ff[4]+w2*ff[7];
            f2=w0*ff[2]+w1*ff[5]+w2*ff[8];
        }
        int bo=p*3*HW + y*IMW + x;
        g_feats[bo      ]=f0;
        g_feats[bo+  HW ]=f1;
        g_feats[bo+2*HW ]=f2;
    }
}

// ---------------- unified single-launch kernel ----------------
struct GeomRaster {
    float  sv[NVERT*3];
    float4 s0[NFACE], s1[NFACE], s2[NFACE];
    int    sid[NFACE];
    float  R[9], T[3];
    int    warp_cnt[8], warp_off[8], chunk_base;
};
struct Post { float bufA[38*160]; float bufB[36*160]; };
union UShared { GeomRaster g; Post p; };

__global__ void __launch_bounds__(256,3) k_all(const float* __restrict__ uv,
                                               const int* __restrict__ faces,
                                               const float* __restrict__ quat,
                                               const float* __restrict__ trans,
                                               const float* __restrict__ ffeat,
                                               float* __restrict__ out){
    __shared__ UShared u;
    int bx=blockIdx.x;
    int p=bx/20, band=bx%20, y0=band*8;
    int tid=threadIdx.x;
    int tx=tid&31, ty=tid>>5;
    int lane=tid&31, wid=tid>>5;

    // ---- phase 1: per-block geometry (redundant per band, no global traffic) ----
    if(tid==0){
        compute_RT(p, quat, trans, u.g.R, u.g.T);
        u.g.chunk_base=0;
    }
    __syncthreads();
    for(int n=tid; n<NVERT; n+=256){
        float ux=uv[n*3+0], uy=uv[n*3+1], uz=uv[n*3+2];
        u.g.sv[n*3+0]=u.g.R[0]*ux+u.g.R[1]*uy+u.g.R[2]*uz + u.g.T[0];
        u.g.sv[n*3+1]=u.g.R[3]*ux+u.g.R[4]*uy+u.g.R[5]*uz + u.g.T[1];
        u.g.sv[n*3+2]=u.g.R[6]*ux+u.g.R[7]*uy+u.g.R[8]*uz + u.g.T[2];
    }
    __syncthreads();

    float pyc = 1.0f - ((float)y0+3.5f)*STEP;
    float pyr = 3.5f*STEP + 1e-4f;
    const float TAU = -0.002f;

    for(int base=0; base<NFACE; base+=256){
        int fidx=base+tid;
        bool keep=false;
        float4 r0,r1,r2;
        if(fidx<NFACE){
            if(face_record(u.g.sv, faces, fidx, r0, r1, r2)){
                float u0=r0.x + fabsf(r0.y) + r0.z*pyc + fabsf(r0.z)*pyr;
                float u1=r1.x + fabsf(r1.y) + r1.z*pyc + fabsf(r1.z)*pyr;
                float u2=r2.x + fabsf(r2.y) + r2.z*pyc + fabsf(r2.z)*pyr;
                keep = fminf(u0,fminf(u1,u2)) >= TAU;
            }
        }
        unsigned bal=__ballot_sync(0xffffffffu, keep);
        if(lane==0) u.g.warp_cnt[wid]=__popc(bal);
        __syncthreads();
        if(tid==0){
            int a=u.g.chunk_base;
            for(int w=0;w<8;w++){ u.g.warp_off[w]=a; a+=u.g.warp_cnt[w]; }
            u.g.chunk_base=a;
        }
        __syncthreads();
        if(keep){
            int pos=u.g.warp_off[wid]+__popc(bal&((1u<<lane)-1u));
            u.g.s0[pos]=r0; u.g.s1[pos]=r1; u.g.s2[pos]=r2; u.g.sid[pos]=fidx;
        }
        __syncthreads();
    }
    int m=u.g.chunk_base;

    // ---- phase 2: raster ----
    raster_pixels(u.g.s0, u.g.s1, u.g.s2, u.g.sid, m, p, y0, tx, ty, ffeat);

    // ---- grid barrier (all 320 blocks co-resident by launch_bounds/occupancy) ----
    __syncthreads();
    __threadfence();
    if(tid==0){
        unsigned arrival=atomicAdd(&g_count, 1u);
        unsigned target=(arrival/GRID_ALL + 1u)*GRID_ALL;
        while(*((volatile unsigned*)&g_count) < target) __nanosleep(32);
    }
    __syncthreads();

    // ---- phase 3: post (2 tasks per block) ----
    for(int t=bx; t<640; t+=GRID_ALL){
        int tile=t%10, task=t/10;
        __syncthreads();
        post_task(u.p.bufA, u.p.bufB, task, tile, out, tid);
    }
}

// ================= fallback 3-kernel path (round-6, proven) =================
__global__ void __launch_bounds__(640) k_geom(const float* __restrict__ uv,
                                              const int* __restrict__ faces,
                                              const float* __restrict__ quat,
                                              const float* __restrict__ trans){
    int p=blockIdx.x; int i=threadIdx.x;
    __shared__ float sR[9], sT[3];
    __shared__ float sv[NVERT*3];
    __shared__ int wcnt[20], wbase[20];
    if(i==0) compute_RT(p, quat, trans, sR, sT);
    __syncthreads();
    for(int n=i; n<NVERT; n+=640){
        float ux=uv[n*3+0], uy=uv[n*3+1], uz=uv[n*3+2];
        sv[n*3+0]=sR[0]*ux+sR[1]*uy+sR[2]*uz + sT[0];
        sv[n*3+1]=sR[3]*ux+sR[4]*uy+sR[5]*uz + sT[1];
        sv[n*3+2]=sR[6]*ux+sR[7]*uy+sR[8]*uz + sT[2];
    }
    __syncthreads();
    int lane=i&31, wid=i>>5;
    float4 r0,r1,r2;
    bool valid=face_record(sv, faces, i, r0, r1, r2);
    unsigned bal=__ballot_sync(0xffffffffu, valid);
    if(lane==0) wcnt[wid]=__popc(bal);
    __syncthreads();
    if(i==0){
        int acc=0;
        for(int w=0;w<20;w++){ wbase[w]=acc; acc+=wcnt[w]; }
        g_nvalid[p]=acc;
    }
    __syncthreads();
    if(valid){
        int pos=wbase[wid]+__popc(bal&((1u<<lane)-1u));
        float4* rec=&g_faceb[(p*NFACE+pos)*4];
        rec[0]=r0; rec[1]=r1; rec[2]=r2;
        rec[3]=make_float4(__int_as_float(i), 0.f, 0.f, 0.f);
    }
}

__global__ void __launch_bounds__(256) k_raster(const float* __restrict__ ffeat){
    int p=blockIdx.z;
    int y0=blockIdx.y*8;
    int tx=threadIdx.x;
    int tid=threadIdx.y*32+tx;
    int lane=tid&31, wid=tid>>5;

    __shared__ float4 s0[NFACE], s1[NFACE], s2[NFACE];
    __shared__ int   sid[NFACE];
    __shared__ int   warp_cnt[8], warp_off[8];
    __shared__ int   chunk_base;

    int n=g_nvalid[p];
    const float4* src=&g_faceb[p*NFACE*4];
    if(tid==0) chunk_base=0;
    __syncthreads();

    float pyc = 1.0f - ((float)y0+3.5f)*STEP;
    float pyr = 3.5f*STEP + 1e-4f;
    const float TAU = -0.002f;

    for(int base=0; base<n; base+=256){
        int f=base+tid;
        bool keep=false;
        float4 r0,r1,r2,r3;
        if(f<n){
            r0=src[4*f+0]; r1=src[4*f+1]; r2=src[4*f+2]; r3=src[4*f+3];
            float u0=r0.x + fabsf(r0.y) + r0.z*pyc + fabsf(r0.z)*pyr;
            float u1=r1.x + fabsf(r1.y) + r1.z*pyc + fabsf(r1.z)*pyr;
            float u2=r2.x + fabsf(r2.y) + r2.z*pyc + fabsf(r2.z)*pyr;
            keep = fminf(u0,fminf(u1,u2)) >= TAU;
        }
        unsigned bal=__ballot_sync(0xffffffffu, keep);
        if(lane==0) warp_cnt[wid]=__popc(bal);
        __syncthreads();
        if(tid==0){
            int a=chunk_base;
            for(int w=0;w<8;w++){ warp_off[w]=a; a+=warp_cnt[w]; }
            chunk_base=a;
        }
        __syncthreads();
        if(keep){
            int pos=warp_off[wid]+__popc(bal&((1u<<lane)-1u));
            s0[pos]=r0; s1[pos]=r1; s2[pos]=r2; sid[pos]=__float_as_int(r3.x);
        }
        __syncthreads();
    }
    raster_pixels(s0, s1, s2, sid, chunk_base, p, y0, tx, threadIdx.y, ffeat);
}

__global__ void __launch_bounds__(256) k_post(float* __restrict__ out){
    __shared__ float bufA[38*160];
    __shared__ float bufB[36*160];
    post_task(bufA, bufB, blockIdx.y, blockIdx.x, out, threadIdx.x);
}

// ---------------- launch ----------------
extern "C" void kernel_launch(void* const* d_in, const int* in_sizes, int n_in,
                              void* d_out, int out_size) {
    const float* trans=(const float*)d_in[0];
    const float* quat =(const float*)d_in[1];
    const float* uv   =(const float*)d_in[2];
    const float* ffeat=(const float*)d_in[3];
    const int*   faces=(const int*)  d_in[4];
    float* out=(float*)d_out;

    // verify all 320 blocks of k_all can be co-resident (needed for the spin barrier)
    int dev=0; cudaGetDevice(&dev);
    int nsm=0; cudaDeviceGetAttribute(&nsm, cudaDevAttrMultiProcessorCount, dev);
    int per_sm=0;
    cudaOccupancyMaxActiveBlocksPerMultiprocessor(&per_sm, k_all, 256, 0);
    if((long)per_sm*nsm >= GRID_ALL){
        k_all<<<GRID_ALL, 256>>>(uv, faces, quat, trans, ffeat, out);
    } else {
        k_geom<<<NPASS, 640>>>(uv, faces, quat, trans);
        k_raster<<<dim3(1,20,NPASS), dim3(32,8)>>>(ffeat);
        k_post<<<dim3(10,64), 256>>>(out);
    }
}